// round 1
// baseline (speedup 1.0000x reference)
#include <cuda_runtime.h>
#include <cuda_bf16.h>

// ---------------------------------------------------------------------------
// Net_autoencpsdhigh: fused SSDR/LBS + details net on GB300.
// Round 0 baseline: fp32 with f32x2 packed FFMA in the two big GEMM-like loops.
//
// Stages:
//  k_init     : zero loss accumulators
//  k_prep     : per (b, joint-tile): field_input einsum + 2-layer MLP +
//               Euler->R, builds affine A[b,j,12] = [R | t]
//  k_dk_*     : detailkey = tm.reshape(64,6016) @ Wd + bd  (2-stage, no atomics)
//  k_skin     : out_pc = blended-affine(sw @ A) applied to rest_verts
//  k_detail   : out_pc += (dk @ DPSD)*std+mean; fused L1-loss + sum(DPSD^2)
//  k_final    : loss scalar
// ---------------------------------------------------------------------------

#define Bn    64
#define Pn    12273
#define Jn    80
#define MOTn  94
#define NKEY  340          // NB*WN
#define NCOLS (Pn * 3)     // 36819

// ---- scratch (device globals; no allocations allowed) ----------------------
__device__ float  g_A[Bn * Jn * 12];              // affine per (b,j)
__device__ float  g_dkp[32 * 4 * 16 * NKEY];      // dk partials [chunk][bg][bb][m]
__device__ float2 g_dkd[NKEY * Bn];               // dk duplicated-pair [m][b]
__device__ float  g_l1, g_dsq;

// ---- f32x2 helpers ----------------------------------------------------------
__device__ __forceinline__ unsigned long long pack2(float a, float b) {
    unsigned long long r;
    asm("mov.b64 %0, {%1, %2};" : "=l"(r) : "f"(a), "f"(b));
    return r;
}
__device__ __forceinline__ void unpack2(unsigned long long v, float& a, float& b) {
    asm("mov.b64 {%0, %1}, %2;" : "=f"(a), "=f"(b) : "l"(v));
}
__device__ __forceinline__ void fma2(unsigned long long& d,
                                     unsigned long long a, unsigned long long b) {
    asm("fma.rn.f32x2 %0, %1, %2, %0;" : "+l"(d) : "l"(a), "l"(b));
}

// ---------------------------------------------------------------------------
__global__ void k_init() {
    if (threadIdx.x == 0) { g_l1 = 0.f; g_dsq = 0.f; }
}

// ---------------------------------------------------------------------------
// k_prep: grid (10 l-tiles, 64 b), 256 threads. Dynamic smem ~64.8KB.
__global__ void k_prep(const float* __restrict__ tmtemp, const float* __restrict__ mwl,
                       const float* __restrict__ query,  const float* __restrict__ W1,
                       const float* __restrict__ b1,     const float* __restrict__ W2,
                       const float* __restrict__ b2,
                       const float* __restrict__ cps, const float* __restrict__ cpm,
                       const float* __restrict__ cts, const float* __restrict__ ctm)
{
    extern __shared__ float sm[];
    float* tm_s  = sm;                      // 94*64
    float* W1_s  = tm_s  + 94 * 64;         // 67*128
    float* mw_s  = W1_s  + 67 * 128;        // 8*94
    float* h_s   = mw_s  + 8 * 94;          // 8*68 (query(3) + field(64))
    float* hid_s = h_s   + 8 * 68;          // 2*128
    float* pr_s  = hid_s + 2 * 128;         // 8*6

    const int tid = threadIdx.x;
    const int b   = blockIdx.y;
    const int l0  = blockIdx.x * 8;

    for (int i = tid; i < 94 * 64; i += 256)  tm_s[i] = tmtemp[b * 6016 + i];
    for (int i = tid; i < 67 * 128; i += 256) W1_s[i] = W1[i];
    for (int i = tid; i < 8 * 94; i += 256) {
        int ll = i / 94, jj = i - ll * 94;
        mw_s[i] = fmaxf(mwl[(l0 + ll) * 94 + jj], 0.f);
    }
    if (tid < 24) {
        int ll = tid / 3, x = tid - ll * 3;
        h_s[ll * 68 + x] = query[((b * 80) + l0 + ll) * 3 + x];
    }
    __syncthreads();

    // field_input[l,k] = sum_j relu(mwl[l,j]) * tm[j,k]
    #pragma unroll
    for (int rep = 0; rep < 2; rep++) {
        int idx = rep * 256 + tid;
        int ll = idx >> 6, k = idx & 63;
        float s = 0.f;
        #pragma unroll 2
        for (int jm = 0; jm < 94; jm++)
            s = fmaf(mw_s[ll * 94 + jm], tm_s[jm * 64 + k], s);
        h_s[ll * 68 + 3 + k] = s;
    }
    __syncthreads();

    // MLP: hid = relu(h@W1+b1); pred_rt = hid@W2+b2 (two joints per pass)
    for (int lp = 0; lp < 4; lp++) {
        int lsub = tid >> 7;
        int ll = lp * 2 + lsub;
        int h  = tid & 127;
        float acc = b1[h];
        for (int i = 0; i < 67; i++)
            acc = fmaf(h_s[ll * 68 + i], W1_s[i * 128 + h], acc);
        hid_s[lsub * 128 + h] = fmaxf(acc, 0.f);
        __syncthreads();
        if (tid < 12) {
            int l2 = tid / 6, o = tid - l2 * 6;
            float s = b2[o];
            for (int hh = 0; hh < 128; hh++)
                s = fmaf(hid_s[l2 * 128 + hh], W2[hh * 6 + o], s);
            pr_s[(lp * 2 + l2) * 6 + o] = s;
        }
        __syncthreads();
    }

    // Euler (deg) -> R, build affine [R|t]
    if (tid < 8) {
        const int ll = tid, gl = l0 + ll;
        const float DEG = 0.017453292519943295f;
        float px = fmaf(pr_s[ll * 6 + 0], cps[0], cpm[0]) * DEG;
        float py = fmaf(pr_s[ll * 6 + 1], cps[1], cpm[1]) * DEG;
        float pz = fmaf(pr_s[ll * 6 + 2], cps[2], cpm[2]) * DEG;
        float qx = h_s[ll * 68 + 0], qy = h_s[ll * 68 + 1], qz = h_s[ll * 68 + 2];
        float t0 = (qx + pr_s[ll * 6 + 3]) * cts[0] + ctm[0];
        float t1 = (qy + pr_s[ll * 6 + 4]) * cts[1] + ctm[1];
        float t2 = (qz + pr_s[ll * 6 + 5]) * cts[2] + ctm[2];
        float sx, cx, sy, cy, sz, cz;
        sincosf(px, &sx, &cx);
        sincosf(py, &sy, &cy);
        sincosf(pz, &sz, &cz);
        float* A = g_A + ((b * 80) + gl) * 12;
        A[0] = cz * cy; A[1] = cz * sy * sx - sz * cx; A[2] = cz * sy * cx + sz * sx;
        A[3] = sz * cy; A[4] = sz * sy * sx + cz * cx; A[5] = sz * sy * cx - cz * sx;
        A[6] = -sy;     A[7] = cy * sx;                A[8] = cy * cx;
        A[9] = t0; A[10] = t1; A[11] = t2;
    }
}

// ---------------------------------------------------------------------------
// k_dk_partial: grid (32 i-chunks, 4 b-groups), 384 threads (340 active = m).
__global__ void k_dk_partial(const float* __restrict__ tmtemp, const float* __restrict__ Wd)
{
    __shared__ __align__(16) float2 tm2_s[8 * 188];
    const int tid = threadIdx.x;
    const int c = blockIdx.x, g = blockIdx.y;
    const int i0 = c * 188;
    for (int i = tid; i < 8 * 188; i += 384) {
        int bb2 = i / 188, ii = i - bb2 * 188;
        int b0 = g * 16 + bb2 * 2;
        tm2_s[i] = make_float2(tmtemp[b0 * 6016 + i0 + ii],
                               tmtemp[(b0 + 1) * 6016 + i0 + ii]);
    }
    __syncthreads();
    if (tid < NKEY) {
        unsigned long long acc[8];
        #pragma unroll
        for (int q = 0; q < 8; q++) acc[q] = 0ull;
        const unsigned long long* tp = (const unsigned long long*)tm2_s;
        for (int ii = 0; ii < 188; ii++) {
            float w = Wd[(i0 + ii) * NKEY + tid];
            unsigned long long w2 = pack2(w, w);
            #pragma unroll
            for (int q = 0; q < 8; q++) fma2(acc[q], tp[q * 188 + ii], w2);
        }
        float* outp = g_dkp + ((c * 4 + g) * 16) * NKEY + tid;
        #pragma unroll
        for (int q = 0; q < 8; q++) {
            float v0, v1; unpack2(acc[q], v0, v1);
            outp[(2 * q) * NKEY]     = v0;
            outp[(2 * q + 1) * NKEY] = v1;
        }
    }
}

__global__ void k_dk_combine(const float* __restrict__ bd)
{
    int idx = blockIdx.x * 256 + threadIdx.x;
    if (idx >= Bn * NKEY) return;
    int b = idx / NKEY, m = idx - b * NKEY;
    float v = bd[m];
    int gg = b >> 4, bb = b & 15;
    #pragma unroll
    for (int cc = 0; cc < 32; cc++)
        v += g_dkp[((cc * 4 + gg) * 16 + bb) * NKEY + m];
    g_dkd[m * Bn + b] = make_float2(v, v);
}

// ---------------------------------------------------------------------------
// k_skin: grid 384 p-tiles (32 p), 128 threads. thread = (p_local, b-lane of 4).
__global__ void k_skin(const float* __restrict__ skinw, const float* __restrict__ rest,
                       float* __restrict__ outp)
{
    __shared__ float sw_s[32 * 81];
    __shared__ __align__(16) float A_s[4 * 960];
    const int tid = threadIdx.x;
    const int p0 = blockIdx.x * 32;
    const int np = min(32, Pn - p0);
    const int pl = tid & 31, bg = tid >> 5;

    for (int i = tid; i < np * 80; i += 128) {
        int pp = i / 80, j = i - pp * 80;
        sw_s[pp * 81 + j] = skinw[(p0 + pp) * 80 + j];
    }
    float rvx = 0.f, rvy = 0.f, rvz = 0.f;
    const bool act = pl < np;
    if (act) {
        rvx = rest[(p0 + pl) * 3 + 0];
        rvy = rest[(p0 + pl) * 3 + 1];
        rvz = rest[(p0 + pl) * 3 + 2];
    }
    for (int bs = 0; bs < 16; bs++) {
        __syncthreads();
        for (int i = tid; i < 4 * 960; i += 128) A_s[i] = g_A[bs * 4 * 960 + i];
        __syncthreads();
        const float* Ab = A_s + bg * 960;
        unsigned long long m01 = 0, m23 = 0, m45 = 0, m67 = 0, m89 = 0, mAB = 0;
        const float* swp = sw_s + pl * 81;
        #pragma unroll 4
        for (int j = 0; j < 80; j++) {
            float w = swp[j];
            unsigned long long w2 = pack2(w, w);
            const ulonglong2* ap = (const ulonglong2*)(Ab + j * 12);
            ulonglong2 q0 = ap[0], q1 = ap[1], q2 = ap[2];
            fma2(m01, q0.x, w2); fma2(m23, q0.y, w2);
            fma2(m45, q1.x, w2); fma2(m67, q1.y, w2);
            fma2(m89, q2.x, w2); fma2(mAB, q2.y, w2);
        }
        float m0, m1, m2, m3, m4, m5, m6, m7, m8, m9, mA, mB;
        unpack2(m01, m0, m1); unpack2(m23, m2, m3); unpack2(m45, m4, m5);
        unpack2(m67, m6, m7); unpack2(m89, m8, m9); unpack2(mAB, mA, mB);
        float ox = fmaf(m0, rvx, fmaf(m1, rvy, fmaf(m2, rvz, m9)));
        float oy = fmaf(m3, rvx, fmaf(m4, rvy, fmaf(m5, rvz, mA)));
        float oz = fmaf(m6, rvx, fmaf(m7, rvy, fmaf(m8, rvz, mB)));
        if (act) {
            int b = bs * 4 + bg;
            int base = (b * Pn + p0 + pl) * 3;
            outp[base]     = ox;
            outp[base + 1] = oy;
            outp[base + 2] = oz;
        }
    }
}

// ---------------------------------------------------------------------------
// k_detail: grid 288 column-tiles (128 cols), 128 threads.
// thread = (bgrp of 8 b) x (8 adjacent cols = 4 f32x2 pairs); acc 8x4 f32x2.
__global__ void k_detail(const float* __restrict__ DPSD, const float* __restrict__ inpc,
                         const float* __restrict__ sstd, const float* __restrict__ smean,
                         float* __restrict__ outp)
{
    __shared__ __align__(16) float  Ds[32 * 128];
    __shared__ __align__(16) float2 Ks[32 * 64];
    __shared__ float sm6[6];
    __shared__ float red[2][4];

    const int tid = threadIdx.x;
    const int cg = tid & 15, bgrp = tid >> 4;
    const int c0 = blockIdx.x * 128;
    if (tid < 3)      sm6[tid] = sstd[tid];
    else if (tid < 6) sm6[tid] = smean[tid - 3];

    unsigned long long acc[8][4];
    #pragma unroll
    for (int q = 0; q < 8; q++)
        #pragma unroll
        for (int r = 0; r < 4; r++) acc[q][r] = 0ull;
    float dsq = 0.f;

    for (int m0 = 0; m0 < NKEY; m0 += 32) {
        const int mc = min(32, NKEY - m0);
        __syncthreads();
        for (int i = tid; i < mc * 128; i += 128) {
            int mm = i >> 7;            // column within tile == tid
            int cpos = c0 + tid;
            float v = (cpos < NCOLS) ? DPSD[(m0 + mm) * NCOLS + cpos] : 0.f;
            Ds[mm * 128 + tid] = v;
            dsq = fmaf(v, v, dsq);
        }
        for (int i = tid; i < mc * 64; i += 128) {
            int mm = i >> 6, bb = i & 63;
            Ks[mm * 64 + bb] = g_dkd[(m0 + mm) * 64 + bb];
        }
        __syncthreads();
        for (int mm = 0; mm < mc; mm++) {
            const ulonglong2* dp = (const ulonglong2*)(Ds + mm * 128 + cg * 8);
            ulonglong2 d01 = dp[0], d23 = dp[1];
            const ulonglong2* kp = (const ulonglong2*)(Ks + mm * 64 + bgrp * 8);
            ulonglong2 k01 = kp[0], k23 = kp[1], k45 = kp[2], k67 = kp[3];
            unsigned long long dv[4] = { d01.x, d01.y, d23.x, d23.y };
            unsigned long long kv[8] = { k01.x, k01.y, k23.x, k23.y,
                                         k45.x, k45.y, k67.x, k67.y };
            #pragma unroll
            for (int q = 0; q < 8; q++)
                #pragma unroll
                for (int r = 0; r < 4; r++) fma2(acc[q][r], kv[q], dv[r]);
        }
    }

    // epilogue: scale/shift detail, add to skinned, fused L1 loss
    float l1 = 0.f;
    const int cb = c0 + cg * 8;
    #pragma unroll
    for (int bb = 0; bb < 8; bb++) {
        int b = bgrp * 8 + bb;
        int base = b * NCOLS;
        #pragma unroll
        for (int pp = 0; pp < 4; pp++) {
            float v0, v1; unpack2(acc[bb][pp], v0, v1);
            int c = cb + pp * 2;
            if (c < NCOLS) {
                int x = c % 3;
                float o = outp[base + c] + fmaf(v0, sm6[x], sm6[3 + x]);
                outp[base + c] = o;
                l1 += fabsf(inpc[base + c] - o);
            }
            if (c + 1 < NCOLS) {
                int x = (c + 1) % 3;
                float o = outp[base + c + 1] + fmaf(v1, sm6[x], sm6[3 + x]);
                outp[base + c + 1] = o;
                l1 += fabsf(inpc[base + c + 1] - o);
            }
        }
    }

    #pragma unroll
    for (int off = 16; off; off >>= 1) {
        l1  += __shfl_down_sync(0xffffffffu, l1,  off);
        dsq += __shfl_down_sync(0xffffffffu, dsq, off);
    }
    int wid = tid >> 5, lane = tid & 31;
    if (lane == 0) { red[0][wid] = l1; red[1][wid] = dsq; }
    __syncthreads();
    if (tid == 0) {
        atomicAdd(&g_l1,  red[0][0] + red[0][1] + red[0][2] + red[0][3]);
        atomicAdd(&g_dsq, red[1][0] + red[1][1] + red[1][2] + red[1][3]);
    }
}

// ---------------------------------------------------------------------------
__global__ void k_final(float* __restrict__ out)
{
    out[0] = g_l1 * (1.f / (64.f * 12273.f * 3.f))
           + 1e-4f * g_dsq * (1.f / (340.f * 12273.f * 3.f));
}

// ---------------------------------------------------------------------------
extern "C" void kernel_launch(void* const* d_in, const int* in_sizes, int n_in,
                              void* d_out, int out_size)
{
    const float* inpc   = (const float*)d_in[0];
    // d_in[1] = t_nor (unused by the reference)
    const float* rest   = (const float*)d_in[2];
    const float* skinw  = (const float*)d_in[3];
    const float* mwl    = (const float*)d_in[4];
    const float* query  = (const float*)d_in[5];
    const float* cps    = (const float*)d_in[6];
    const float* cpm    = (const float*)d_in[7];
    const float* cts    = (const float*)d_in[8];
    const float* ctm    = (const float*)d_in[9];
    const float* W1     = (const float*)d_in[10];
    const float* b1     = (const float*)d_in[11];
    const float* W2     = (const float*)d_in[12];
    const float* b2     = (const float*)d_in[13];
    const float* tmtemp = (const float*)d_in[14];
    const float* Wd     = (const float*)d_in[15];
    const float* bd     = (const float*)d_in[16];
    const float* DPSD   = (const float*)d_in[17];
    const float* sstd   = (const float*)d_in[18];
    const float* smean  = (const float*)d_in[19];

    float* out  = (float*)d_out;
    float* outp = out + 1;   // out[0] = loss, out[1:] = out_pc [B,P,3]

    const int prep_smem = (94 * 64 + 67 * 128 + 8 * 94 + 8 * 68 + 2 * 128 + 48) * 4;
    cudaFuncSetAttribute(k_prep, cudaFuncAttributeMaxDynamicSharedMemorySize, prep_smem);

    k_init<<<1, 32>>>();
    k_prep<<<dim3(10, 64), 256, prep_smem>>>(tmtemp, mwl, query, W1, b1, W2, b2,
                                             cps, cpm, cts, ctm);
    k_dk_partial<<<dim3(32, 4), 384>>>(tmtemp, Wd);
    k_dk_combine<<<85, 256>>>(bd);
    k_skin<<<384, 128>>>(skinw, rest, outp);
    k_detail<<<288, 128>>>(DPSD, inpc, sstd, smean, outp);
    k_final<<<1, 1>>>(out);
}

// round 2
// speedup vs baseline: 1.3349x; 1.3349x over previous
#include <cuda_runtime.h>
#include <cuda_bf16.h>

// ---------------------------------------------------------------------------
// Net_autoencpsdhigh — round 2: occupancy + fma-density + MLP fixes.
//   k_prep       : field einsum + MLP + Euler->affine A[b,j,12]; zeroes accums
//   k_dk_partial : detailkey partials (2-wide unrolled LDG, 256 blocks)
//   k_dk_combine : reduce partials + bias -> g_dkd[m][b] duplicated pairs
//   k_skin       : out_pc = LBS(sw @ A) applied to rest_verts (2p x 1b tiles)
//   k_detail     : out_pc += (dk @ DPSD)*std+mean; fused L1 + DPSD^2 + loss
// ---------------------------------------------------------------------------

#define Bn    64
#define Pn    12273
#define Jn    80
#define MOTn  94
#define NKEY  340          // NB*WN
#define NCOLS (Pn * 3)     // 36819
#define DKCH  64           // dk i-chunks (94 each)

// ---- scratch ----------------------------------------------------------------
__device__ float    g_A[Bn * Jn * 12];
__device__ float    g_dkp[DKCH * 4 * 16 * NKEY];
__device__ float2   g_dkd[NKEY * Bn];
__device__ float    g_l1, g_dsq;
__device__ unsigned g_tick = 0;

// ---- f32x2 helpers ----------------------------------------------------------
__device__ __forceinline__ unsigned long long pack2(float a, float b) {
    unsigned long long r;
    asm("mov.b64 %0, {%1, %2};" : "=l"(r) : "f"(a), "f"(b));
    return r;
}
__device__ __forceinline__ void unpack2(unsigned long long v, float& a, float& b) {
    asm("mov.b64 {%0, %1}, %2;" : "=f"(a), "=f"(b) : "l"(v));
}
__device__ __forceinline__ void fma2(unsigned long long& d,
                                     unsigned long long a, unsigned long long b) {
    asm("fma.rn.f32x2 %0, %1, %2, %0;" : "+l"(d) : "l"(a), "l"(b));
}

// ---------------------------------------------------------------------------
// k_prep: grid (10 l-tiles, 64 b), 256 threads.
__global__ void k_prep(const float* __restrict__ tmtemp, const float* __restrict__ mwl,
                       const float* __restrict__ query,  const float* __restrict__ W1,
                       const float* __restrict__ b1,     const float* __restrict__ W2,
                       const float* __restrict__ b2,
                       const float* __restrict__ cps, const float* __restrict__ cpm,
                       const float* __restrict__ cts, const float* __restrict__ ctm)
{
    extern __shared__ float sm[];
    float* tm_s  = sm;                      // 94*64  = 6016
    float* W1_s  = tm_s  + 94 * 64;         // 67*128 = 8576
    float* mw_s  = W1_s  + 67 * 128;        // 8*94   = 752
    float* h_s   = mw_s  + 8 * 94;          // 8*68   = 544
    float* hid_s = h_s   + 8 * 68;          // 2*128  = 256
    float* pr_s  = hid_s + 2 * 128;         // 48
    float* W2_s  = pr_s  + 48;              // 768
    float* b1_s  = W2_s  + 768;             // 128

    const int tid = threadIdx.x;
    const int b   = blockIdx.y;
    const int l0  = blockIdx.x * 8;

    if (blockIdx.x == 0 && blockIdx.y == 0 && tid == 0) {
        g_l1 = 0.f; g_dsq = 0.f;
    }

    for (int i = tid; i < 94 * 64; i += 256)  tm_s[i] = tmtemp[b * 6016 + i];
    for (int i = tid; i < 67 * 128; i += 256) W1_s[i] = W1[i];
    for (int i = tid; i < 768; i += 256)      W2_s[i] = W2[i];
    if (tid < 128) b1_s[tid] = b1[tid];
    for (int i = tid; i < 8 * 94; i += 256) {
        int ll = i / 94, jj = i - ll * 94;
        mw_s[i] = fmaxf(mwl[(l0 + ll) * 94 + jj], 0.f);
    }
    if (tid < 24) {
        int ll = tid / 3, x = tid - ll * 3;
        h_s[ll * 68 + x] = query[((b * 80) + l0 + ll) * 3 + x];
    }
    __syncthreads();

    // field_input[l,k] = sum_j relu(mwl[l,j]) * tm[j,k]
    #pragma unroll
    for (int rep = 0; rep < 2; rep++) {
        int idx = rep * 256 + tid;
        int ll = idx >> 6, k = idx & 63;
        float s = 0.f;
        #pragma unroll 2
        for (int jm = 0; jm < 94; jm++)
            s = fmaf(mw_s[ll * 94 + jm], tm_s[jm * 64 + k], s);
        h_s[ll * 68 + 3 + k] = s;
    }
    __syncthreads();

    // MLP: two joints per pass
    for (int lp = 0; lp < 4; lp++) {
        int lsub = tid >> 7;
        int ll = lp * 2 + lsub;
        int h  = tid & 127;
        float acc = b1_s[h];
        #pragma unroll 2
        for (int i = 0; i < 67; i++)
            acc = fmaf(h_s[ll * 68 + i], W1_s[i * 128 + h], acc);
        hid_s[lsub * 128 + h] = fmaxf(acc, 0.f);
        __syncthreads();
        // layer 2: 12 dot products of 128, one per 16-lane group
        if (tid < 192) {
            int g = tid >> 4, lane = tid & 15;
            int l2 = g / 6, o = g - l2 * 6;
            float s = 0.f;
            #pragma unroll
            for (int t = 0; t < 8; t++)
                s = fmaf(hid_s[l2 * 128 + lane + 16 * t],
                         W2_s[(lane + 16 * t) * 6 + o], s);
            #pragma unroll
            for (int off = 8; off; off >>= 1)
                s += __shfl_down_sync(0xffffffffu, s, off, 16);
            if (lane == 0)
                pr_s[(lp * 2 + l2) * 6 + o] = s + __ldg(&b2[o]);
        }
        __syncthreads();
    }

    // Euler (deg) -> R, build affine [R|t]
    if (tid < 8) {
        const int ll = tid, gl = l0 + ll;
        const float DEG = 0.017453292519943295f;
        float px = fmaf(pr_s[ll * 6 + 0], cps[0], cpm[0]) * DEG;
        float py = fmaf(pr_s[ll * 6 + 1], cps[1], cpm[1]) * DEG;
        float pz = fmaf(pr_s[ll * 6 + 2], cps[2], cpm[2]) * DEG;
        float qx = h_s[ll * 68 + 0], qy = h_s[ll * 68 + 1], qz = h_s[ll * 68 + 2];
        float t0 = (qx + pr_s[ll * 6 + 3]) * cts[0] + ctm[0];
        float t1 = (qy + pr_s[ll * 6 + 4]) * cts[1] + ctm[1];
        float t2 = (qz + pr_s[ll * 6 + 5]) * cts[2] + ctm[2];
        float sx, cx, sy, cy, sz, cz;
        sincosf(px, &sx, &cx);
        sincosf(py, &sy, &cy);
        sincosf(pz, &sz, &cz);
        float* A = g_A + ((b * 80) + gl) * 12;
        A[0] = cz * cy; A[1] = cz * sy * sx - sz * cx; A[2] = cz * sy * cx + sz * sx;
        A[3] = sz * cy; A[4] = sz * sy * sx + cz * cx; A[5] = sz * sy * cx - cz * sx;
        A[6] = -sy;     A[7] = cy * sx;                A[8] = cy * cx;
        A[9] = t0; A[10] = t1; A[11] = t2;
    }
}

// ---------------------------------------------------------------------------
// k_dk_partial: grid (64 i-chunks of 94, 4 b-groups), 384 threads (340 = m).
__global__ void k_dk_partial(const float* __restrict__ tmtemp, const float* __restrict__ Wd)
{
    __shared__ __align__(16) float2 tm2_s[8 * 94];
    const int tid = threadIdx.x;
    const int c = blockIdx.x, g = blockIdx.y;
    const int i0 = c * 94;
    for (int i = tid; i < 8 * 94; i += 384) {
        int bb2 = i / 94, ii = i - bb2 * 94;
        int b0 = g * 16 + bb2 * 2;
        tm2_s[i] = make_float2(tmtemp[b0 * 6016 + i0 + ii],
                               tmtemp[(b0 + 1) * 6016 + i0 + ii]);
    }
    __syncthreads();
    if (tid < NKEY) {
        unsigned long long acc[8];
        #pragma unroll
        for (int q = 0; q < 8; q++) acc[q] = 0ull;
        const unsigned long long* tp = (const unsigned long long*)tm2_s;
        const float* wp = Wd + (long long)i0 * NKEY + tid;
        for (int ii = 0; ii < 94; ii += 2) {
            float wA = wp[ii * NKEY];
            float wB = wp[(ii + 1) * NKEY];
            unsigned long long w2A = pack2(wA, wA);
            unsigned long long w2B = pack2(wB, wB);
            #pragma unroll
            for (int q = 0; q < 8; q++) fma2(acc[q], tp[q * 94 + ii], w2A);
            #pragma unroll
            for (int q = 0; q < 8; q++) fma2(acc[q], tp[q * 94 + ii + 1], w2B);
        }
        float* outp = g_dkp + ((c * 4 + g) * 16) * NKEY + tid;
        #pragma unroll
        for (int q = 0; q < 8; q++) {
            float v0, v1; unpack2(acc[q], v0, v1);
            outp[(2 * q) * NKEY]     = v0;
            outp[(2 * q + 1) * NKEY] = v1;
        }
    }
}

__global__ void k_dk_combine(const float* __restrict__ bd)
{
    int idx = blockIdx.x * 256 + threadIdx.x;
    if (idx >= Bn * NKEY) return;
    int b = idx / NKEY, m = idx - b * NKEY;
    float v = bd[m];
    int gg = b >> 4, bb = b & 15;
    #pragma unroll 8
    for (int cc = 0; cc < DKCH; cc++)
        v += g_dkp[((cc * 4 + gg) * 16 + bb) * NKEY + m];
    g_dkd[m * Bn + b] = make_float2(v, v);
}

// ---------------------------------------------------------------------------
// k_skin: grid (192 p-tiles of 64, 4 b-groups of 16), 128 threads.
// thread = (pl in 0..31 -> rows pl, pl+32) x (bg in 0..3); bs loop covers 4 b-quads.
__global__ void k_skin(const float* __restrict__ skinw, const float* __restrict__ rest,
                       float* __restrict__ outp)
{
    __shared__ float sw_s[64 * 81];
    __shared__ __align__(16) float A_s[4 * 960];
    const int tid = threadIdx.x;
    const int p0 = blockIdx.x * 64;
    const int bq = blockIdx.y;           // 16 b per block
    const int pl = tid & 31, bg = tid >> 5;

    for (int i = tid; i < 64 * 80; i += 128) {
        int pp = i / 80, j = i - pp * 80;
        sw_s[pp * 81 + j] = (p0 + pp < Pn) ? skinw[(p0 + pp) * 80 + j] : 0.f;
    }
    const int pA = p0 + pl, pB = p0 + pl + 32;
    const bool actA = pA < Pn, actB = pB < Pn;
    float rAx = 0.f, rAy = 0.f, rAz = 0.f, rBx = 0.f, rBy = 0.f, rBz = 0.f;
    if (actA) { rAx = rest[pA * 3]; rAy = rest[pA * 3 + 1]; rAz = rest[pA * 3 + 2]; }
    if (actB) { rBx = rest[pB * 3]; rBy = rest[pB * 3 + 1]; rBz = rest[pB * 3 + 2]; }

    for (int bs = 0; bs < 4; bs++) {
        __syncthreads();
        for (int i = tid; i < 4 * 960; i += 128)
            A_s[i] = g_A[(bq * 16 + bs * 4) * 960 + i];
        __syncthreads();

        const float* Ab = A_s + bg * 960;
        unsigned long long mA01 = 0, mA23 = 0, mA45 = 0, mA67 = 0, mA89 = 0, mAAB = 0;
        unsigned long long mB01 = 0, mB23 = 0, mB45 = 0, mB67 = 0, mB89 = 0, mBAB = 0;
        const float* swA = sw_s + pl * 81;
        const float* swB = sw_s + (pl + 32) * 81;
        #pragma unroll 4
        for (int j = 0; j < 80; j++) {
            float wa = swA[j], wb = swB[j];
            unsigned long long w2a = pack2(wa, wa);
            unsigned long long w2b = pack2(wb, wb);
            const ulonglong2* ap = (const ulonglong2*)(Ab + j * 12);
            ulonglong2 q0 = ap[0], q1 = ap[1], q2 = ap[2];
            fma2(mA01, q0.x, w2a); fma2(mA23, q0.y, w2a);
            fma2(mA45, q1.x, w2a); fma2(mA67, q1.y, w2a);
            fma2(mA89, q2.x, w2a); fma2(mAAB, q2.y, w2a);
            fma2(mB01, q0.x, w2b); fma2(mB23, q0.y, w2b);
            fma2(mB45, q1.x, w2b); fma2(mB67, q1.y, w2b);
            fma2(mB89, q2.x, w2b); fma2(mBAB, q2.y, w2b);
        }
        const int b = bq * 16 + bs * 4 + bg;
        {
            float m0, m1, m2, m3, m4, m5, m6, m7, m8, m9, mA, mB;
            unpack2(mA01, m0, m1); unpack2(mA23, m2, m3); unpack2(mA45, m4, m5);
            unpack2(mA67, m6, m7); unpack2(mA89, m8, m9); unpack2(mAAB, mA, mB);
            if (actA) {
                int base = (b * Pn + pA) * 3;
                outp[base]     = fmaf(m0, rAx, fmaf(m1, rAy, fmaf(m2, rAz, m9)));
                outp[base + 1] = fmaf(m3, rAx, fmaf(m4, rAy, fmaf(m5, rAz, mA)));
                outp[base + 2] = fmaf(m6, rAx, fmaf(m7, rAy, fmaf(m8, rAz, mB)));
            }
        }
        {
            float m0, m1, m2, m3, m4, m5, m6, m7, m8, m9, mA, mB;
            unpack2(mB01, m0, m1); unpack2(mB23, m2, m3); unpack2(mB45, m4, m5);
            unpack2(mB67, m6, m7); unpack2(mB89, m8, m9); unpack2(mBAB, mA, mB);
            if (actB) {
                int base = (b * Pn + pB) * 3;
                outp[base]     = fmaf(m0, rBx, fmaf(m1, rBy, fmaf(m2, rBz, m9)));
                outp[base + 1] = fmaf(m3, rBx, fmaf(m4, rBy, fmaf(m5, rBz, mA)));
                outp[base + 2] = fmaf(m6, rBx, fmaf(m7, rBy, fmaf(m8, rBz, mB)));
            }
        }
    }
}

// ---------------------------------------------------------------------------
// k_detail: grid 288 col-tiles (128 cols), 256 threads.
// thread = (bgrp of 4 b) x (8 adjacent cols = 4 f32x2 pairs); acc 4x4 f32x2.
__global__ void k_detail(const float* __restrict__ DPSD, const float* __restrict__ inpc,
                         const float* __restrict__ sstd, const float* __restrict__ smean,
                         float* __restrict__ out, float* __restrict__ outp)
{
    __shared__ __align__(16) float  Ds[32 * 128];
    __shared__ __align__(16) float2 Ks[32 * 64];
    __shared__ float sm6[6];
    __shared__ float red[2][8];

    const int tid = threadIdx.x;
    const int cg = tid & 15, bgrp = tid >> 4;     // 16 col-groups x 16 b-groups
    const int c0 = blockIdx.x * 128;
    if (tid < 3)      sm6[tid] = sstd[tid];
    else if (tid < 6) sm6[tid] = smean[tid - 3];

    unsigned long long acc[4][4];
    #pragma unroll
    for (int q = 0; q < 4; q++)
        #pragma unroll
        for (int r = 0; r < 4; r++) acc[q][r] = 0ull;
    float dsq = 0.f;

    const int mycol = c0 + (tid & 127);
    for (int m0 = 0; m0 < NKEY; m0 += 32) {
        const int mc = min(32, NKEY - m0);
        __syncthreads();
        for (int i = tid; i < mc * 128; i += 256) {
            int mm = i >> 7, cc = i & 127;
            float v = (c0 + cc < NCOLS) ? DPSD[(long long)(m0 + mm) * NCOLS + c0 + cc] : 0.f;
            Ds[mm * 128 + cc] = v;
            dsq = fmaf(v, v, dsq);
        }
        for (int i = tid; i < mc * 64; i += 256) {
            int mm = i >> 6, bb = i & 63;
            Ks[mm * 64 + bb] = g_dkd[(m0 + mm) * 64 + bb];
        }
        __syncthreads();
        for (int mm = 0; mm < mc; mm++) {
            const ulonglong2* dp = (const ulonglong2*)(Ds + mm * 128 + cg * 8);
            ulonglong2 d01 = dp[0], d23 = dp[1];
            const ulonglong2* kp = (const ulonglong2*)(Ks + mm * 64 + bgrp * 4);
            ulonglong2 k01 = kp[0], k23 = kp[1];
            unsigned long long dv[4] = { d01.x, d01.y, d23.x, d23.y };
            unsigned long long kv[4] = { k01.x, k01.y, k23.x, k23.y };
            #pragma unroll
            for (int q = 0; q < 4; q++)
                #pragma unroll
                for (int r = 0; r < 4; r++) fma2(acc[q][r], kv[q], dv[r]);
        }
    }

    // epilogue: scale/shift detail, add to skinned, fused L1 loss
    float l1 = 0.f;
    const int cb = c0 + cg * 8;
    #pragma unroll
    for (int qb = 0; qb < 4; qb++) {
        int b = bgrp * 4 + qb;
        long long base = (long long)b * NCOLS;
        #pragma unroll
        for (int pp = 0; pp < 4; pp++) {
            float v0, v1; unpack2(acc[qb][pp], v0, v1);
            int c = cb + pp * 2;
            if (c < NCOLS) {
                int x = c % 3;
                float o = outp[base + c] + fmaf(v0, sm6[x], sm6[3 + x]);
                outp[base + c] = o;
                l1 += fabsf(inpc[base + c] - o);
            }
            if (c + 1 < NCOLS) {
                int x = (c + 1) % 3;
                float o = outp[base + c + 1] + fmaf(v1, sm6[x], sm6[3 + x]);
                outp[base + c + 1] = o;
                l1 += fabsf(inpc[base + c + 1] - o);
            }
        }
    }
    (void)mycol;

    #pragma unroll
    for (int off = 16; off; off >>= 1) {
        l1  += __shfl_down_sync(0xffffffffu, l1,  off);
        dsq += __shfl_down_sync(0xffffffffu, dsq, off);
    }
    int wid = tid >> 5, lane = tid & 31;
    if (lane == 0) { red[0][wid] = l1; red[1][wid] = dsq; }
    __syncthreads();
    if (tid == 0) {
        float tl1 = 0.f, tdq = 0.f;
        #pragma unroll
        for (int w = 0; w < 8; w++) { tl1 += red[0][w]; tdq += red[1][w]; }
        atomicAdd(&g_l1, tl1);
        atomicAdd(&g_dsq, tdq);
        __threadfence();
        unsigned t = atomicAdd(&g_tick, 1u);
        if (t == gridDim.x - 1) {
            g_tick = 0;
            float fl1 = atomicAdd(&g_l1, 0.f);
            float fdq = atomicAdd(&g_dsq, 0.f);
            out[0] = fl1 * (1.f / (64.f * 12273.f * 3.f))
                   + 1e-4f * fdq * (1.f / (340.f * 12273.f * 3.f));
        }
    }
}

// ---------------------------------------------------------------------------
extern "C" void kernel_launch(void* const* d_in, const int* in_sizes, int n_in,
                              void* d_out, int out_size)
{
    const float* inpc   = (const float*)d_in[0];
    const float* rest   = (const float*)d_in[2];
    const float* skinw  = (const float*)d_in[3];
    const float* mwl    = (const float*)d_in[4];
    const float* query  = (const float*)d_in[5];
    const float* cps    = (const float*)d_in[6];
    const float* cpm    = (const float*)d_in[7];
    const float* cts    = (const float*)d_in[8];
    const float* ctm    = (const float*)d_in[9];
    const float* W1     = (const float*)d_in[10];
    const float* b1     = (const float*)d_in[11];
    const float* W2     = (const float*)d_in[12];
    const float* b2     = (const float*)d_in[13];
    const float* tmtemp = (const float*)d_in[14];
    const float* Wd     = (const float*)d_in[15];
    const float* bd     = (const float*)d_in[16];
    const float* DPSD   = (const float*)d_in[17];
    const float* sstd   = (const float*)d_in[18];
    const float* smean  = (const float*)d_in[19];

    float* out  = (float*)d_out;
    float* outp = out + 1;   // out[0] = loss, out[1:] = out_pc [B,P,3]

    const int prep_smem = (94 * 64 + 67 * 128 + 8 * 94 + 8 * 68 + 2 * 128 + 48
                           + 768 + 128) * 4;
    cudaFuncSetAttribute(k_prep, cudaFuncAttributeMaxDynamicSharedMemorySize, prep_smem);

    k_prep<<<dim3(10, 64), 256, prep_smem>>>(tmtemp, mwl, query, W1, b1, W2, b2,
                                             cps, cpm, cts, ctm);
    k_dk_partial<<<dim3(DKCH, 4), 384>>>(tmtemp, Wd);
    k_dk_combine<<<85, 256>>>(bd);
    k_skin<<<dim3(192, 4), 128>>>(skinw, rest, outp);
    k_detail<<<288, 256>>>(DPSD, inpc, sstd, smean, out, outp);
}